// round 10
// baseline (speedup 1.0000x reference)
#include <cuda_runtime.h>

// IGANN GAM: logits[b] = x[b,:]@a + bias + sum_f fc3_f(relu(fc2_f(relu(x[b,f]*W1_f+b1_f))))
// B=32768, F=256, H=16, fp32.
//
// R7: RPT=4 + k-split (two passes of 4 k-pairs) -> t[4][4]=32 regs,
// fits 3 CTAs/SM at ~85 regs. h1 recomputed per pass (cheap).

typedef unsigned long long ull;

constexpr int B_TOTAL = 32768;
constexpr int F_TOTAL = 256;
constexpr int H       = 16;

constexpr int BLOCK   = 256;
constexpr int RPT     = 4;
constexpr int ROWS    = BLOCK * RPT;        // 1024
constexpr int FCHUNK  = 8;
constexpr int NCHUNK  = F_TOTAL / FCHUNK;   // 32
constexpr int NBTILE  = B_TOTAL / ROWS;     // 32
constexpr int XSTRIDE = FCHUNK + 1;         // 9 (odd: conflict-free col reads)

// smem layout (floats); pair arrays first for 16B alignment
constexpr int W2P_ELE = FCHUNK * H * (H / 2) * 2;  // 2048: [f][h][kp]{lo,hi}
constexpr int W1D_ELE = FCHUNK * H * 2;            // 256 dup pairs
constexpr int W3P_ELE = FCHUNK * (H / 2) * 2;      // 128: [f][kp]{lo,hi}
constexpr int SX_ELE  = ROWS * XSTRIDE;            // 9216
constexpr int SMEM_FLOATS = W2P_ELE + 2 * W1D_ELE + FCHUNK * H + W3P_ELE
                          + 2 * FCHUNK + SX_ELE;
constexpr int SMEM_BYTES  = SMEM_FLOATS * (int)sizeof(float);  // ~48.2KB

__device__ __forceinline__ ull fma2(ull a, ull b, ull c) {
    ull d;
    asm("fma.rn.f32x2 %0, %1, %2, %3;" : "=l"(d) : "l"(a), "l"(b), "l"(c));
    return d;
}
__device__ __forceinline__ ull pack2(float lo, float hi) {
    ull d;
    asm("mov.b64 %0, {%1, %2};" : "=l"(d) : "f"(lo), "f"(hi));
    return d;
}
__device__ __forceinline__ void unpack2(ull v, float& lo, float& hi) {
    asm("mov.b64 {%0, %1}, %2;" : "=f"(lo), "=f"(hi) : "l"(v));
}
__device__ __forceinline__ ull relu2(ull v) {
    float lo, hi;
    unpack2(v, lo, hi);
    return pack2(fmaxf(lo, 0.0f), fmaxf(hi, 0.0f));
}

__global__ void igann_init_kernel(float* __restrict__ out,
                                  const float* __restrict__ bias_b) {
    int i = blockIdx.x * blockDim.x + threadIdx.x;
    if (i < B_TOTAL) out[i] = bias_b[0];
}

__global__ __launch_bounds__(BLOCK, 3)
void igann_kernel(const float* __restrict__ x,
                  const float* __restrict__ linear_a,
                  const float* __restrict__ W1,
                  const float* __restrict__ b1,
                  const float* __restrict__ W2,
                  const float* __restrict__ b2,
                  const float* __restrict__ W3,
                  const float* __restrict__ b3,
                  float* __restrict__ out) {
    extern __shared__ float smem[];
    float* sW2p = smem;                      // [FCHUNK][H][H/2][2]  k-pair interleaved
    float* sW1d = sW2p + W2P_ELE;            // [FCHUNK][H][2] duplicated
    float* sB1d = sW1d + W1D_ELE;            // [FCHUNK][H][2] duplicated
    float* sW3p = sB1d + W1D_ELE;            // [FCHUNK][H/2][2] k-pair
    float* sB2  = sW3p + W3P_ELE;            // [FCHUNK][H] (read as ull pairs)
    float* sB3  = sB2  + FCHUNK * H;         // [FCHUNK]
    float* sA   = sB3  + FCHUNK;             // [FCHUNK]
    float* sx   = sA   + FCHUNK;             // [ROWS][XSTRIDE]

    const int tid  = threadIdx.x;
    const int row0 = blockIdx.x * ROWS;
    const int f0   = blockIdx.y * FCHUNK;

    // ---- stage small weights ----
    {
        const int wbase = f0 * H;
        for (int i = tid; i < FCHUNK * H; i += BLOCK) {
            const float w = W1[wbase + i];
            sW1d[2 * i] = w; sW1d[2 * i + 1] = w;
            const float bb = b1[wbase + i];
            sB1d[2 * i] = bb; sB1d[2 * i + 1] = bb;
            sB2[i]  = b2[wbase + i];
            sW3p[i] = W3[wbase + i];   // [f][h] contiguous == [f][kp]{lo,hi}
        }
        if (tid < FCHUNK) {
            sB3[tid] = b3[f0 + tid];
            sA[tid]  = linear_a[f0 + tid];
        }
    }
    // ---- stage W2 k-pair interleaved: sW2p[f][h][kp] = {W2[f][2kp][h], W2[f][2kp+1][h]}
    for (int i = tid; i < FCHUNK * H * (H / 2); i += BLOCK) {
        const int f  = i >> 7;          // / (H * H/2)
        const int h  = (i >> 3) & 15;
        const int kp = i & 7;
        const float* src = W2 + (f0 + f) * (H * H) + h;
        sW2p[2 * i]     = src[(2 * kp) * H];
        sW2p[2 * i + 1] = src[(2 * kp + 1) * H];
    }
    // ---- stage x tile: float4 global loads ----
    for (int i = tid; i < ROWS * (FCHUNK / 4); i += BLOCK) {
        const int r = i >> 1;           // 2 quads per row
        const int q = i & 1;
        const float4 v = *(const float4*)(x + (row0 + r) * F_TOTAL + f0 + 4 * q);
        float* dst = sx + r * XSTRIDE + 4 * q;
        dst[0] = v.x; dst[1] = v.y; dst[2] = v.z; dst[3] = v.w;
    }
    __syncthreads();

    float accL[RPT];
    ull   accP[RPT];
    #pragma unroll
    for (int r = 0; r < RPT; ++r) { accL[r] = 0.0f; accP[r] = pack2(0.0f, 0.0f); }

    #pragma unroll 1
    for (int f = 0; f < FCHUNK; ++f) {
        float xv0 = sx[(tid + 0 * BLOCK) * XSTRIDE + f];
        float xv1 = sx[(tid + 1 * BLOCK) * XSTRIDE + f];
        float xv2 = sx[(tid + 2 * BLOCK) * XSTRIDE + f];
        float xv3 = sx[(tid + 3 * BLOCK) * XSTRIDE + f];
        const ull xp01 = pack2(xv0, xv1);
        const ull xp23 = pack2(xv2, xv3);

        const ull* w1d = (const ull*)sW1d + f * H;
        const ull* b1d = (const ull*)sB1d + f * H;
        const ull* b2p = (const ull*)(sB2 + f * H);               // 8 k-pairs
        const ull* w3p = (const ull*)sW3p + f * (H / 2);          // 8 k-pairs
        const ulonglong2* w2q = (const ulonglong2*)sW2p + f * 64; // 16h x 4 quads

        // two passes over k-space: pass p covers k-pairs 4p..4p+3
        #pragma unroll 1
        for (int p = 0; p < 2; ++p) {
            ull t[RPT][4];
            #pragma unroll
            for (int j = 0; j < 4; ++j) {
                const ull c = b2p[4 * p + j];
                #pragma unroll
                for (int r = 0; r < RPT; ++r) t[r][j] = c;
            }

            #pragma unroll
            for (int h = 0; h < H; ++h) {
                const ull hp01 = fma2(xp01, w1d[h], b1d[h]);
                const ull hp23 = fma2(xp23, w1d[h], b1d[h]);
                float h0, h1, h2, h3;
                unpack2(hp01, h0, h1);
                unpack2(hp23, h2, h3);
                h0 = fmaxf(h0, 0.0f); h1 = fmaxf(h1, 0.0f);
                h2 = fmaxf(h2, 0.0f); h3 = fmaxf(h3, 0.0f);
                ull d[RPT];
                d[0] = pack2(h0, h0);
                d[1] = pack2(h1, h1);
                d[2] = pack2(h2, h2);
                d[3] = pack2(h3, h3);
                const ulonglong2 wa = w2q[h * 4 + 2 * p];       // k-pairs 4p, 4p+1
                const ulonglong2 wb = w2q[h * 4 + 2 * p + 1];   // k-pairs 4p+2, 4p+3
                #pragma unroll
                for (int r = 0; r < RPT; ++r) {
                    t[r][0] = fma2(d[r], wa.x, t[r][0]);
                    t[r][1] = fma2(d[r], wa.y, t[r][1]);
                    t[r][2] = fma2(d[r], wb.x, t[r][2]);
                    t[r][3] = fma2(d[r], wb.y, t[r][3]);
                }
            }

            // epilogue for this k half
            #pragma unroll
            for (int j = 0; j < 4; ++j) {
                const ull w3 = w3p[4 * p + j];
                #pragma unroll
                for (int r = 0; r < RPT; ++r)
                    accP[r] = fma2(relu2(t[r][j]), w3, accP[r]);
            }
        }

        const float bf = sB3[f];
        const float af = sA[f];
        accL[0] = fmaf(xv0, af, accL[0] + bf);
        accL[1] = fmaf(xv1, af, accL[1] + bf);
        accL[2] = fmaf(xv2, af, accL[2] + bf);
        accL[3] = fmaf(xv3, af, accL[3] + bf);
    }

    #pragma unroll
    for (int r = 0; r < RPT; ++r) {
        float lo, hi;
        unpack2(accP[r], lo, hi);
        atomicAdd(&out[row0 + tid + r * BLOCK], accL[r] + lo + hi);
    }
}

extern "C" void kernel_launch(void* const* d_in, const int* in_sizes, int n_in,
                              void* d_out, int out_size) {
    const float* x        = (const float*)d_in[0];
    const float* linear_a = (const float*)d_in[1];
    const float* bias_b   = (const float*)d_in[2];
    const float* W1       = (const float*)d_in[3];
    const float* b1       = (const float*)d_in[4];
    const float* W2       = (const float*)d_in[5];
    const float* b2       = (const float*)d_in[6];
    const float* W3       = (const float*)d_in[7];
    const float* b3       = (const float*)d_in[8];
    float* out = (float*)d_out;

    cudaFuncSetAttribute(igann_kernel,
                         cudaFuncAttributeMaxDynamicSharedMemorySize, SMEM_BYTES);

    igann_init_kernel<<<(B_TOTAL + 255) / 256, 256>>>(out, bias_b);

    dim3 grid(NBTILE, NCHUNK);
    igann_kernel<<<grid, BLOCK, SMEM_BYTES>>>(x, linear_a, W1, b1, W2, b2, W3, b3, out);
}

// round 12
// speedup vs baseline: 2.8406x; 2.8406x over previous
#include <cuda_runtime.h>

// IGANN GAM: logits[b] = x[b,:]@a + bias + sum_f fc3_f(relu(fc2_f(relu(x[b,f]*W1_f+b1_f))))
// B=32768, F=256, H=16, fp32.
//
// R10: revert R7 k-split (it spilled -> 281MB local traffic). R4 dataflow with
// RPT=2 (t[2][8]=32 regs), explicit double-buffered W2 LDS prefetch, fully
// unrolled h-body, 3 CTAs/SM.

typedef unsigned long long ull;

constexpr int B_TOTAL = 32768;
constexpr int F_TOTAL = 256;
constexpr int H       = 16;

constexpr int BLOCK   = 256;
constexpr int RPT     = 2;
constexpr int ROWS    = BLOCK * RPT;        // 512
constexpr int FCHUNK  = 8;
constexpr int NCHUNK  = F_TOTAL / FCHUNK;   // 32
constexpr int NBTILE  = B_TOTAL / ROWS;     // 64
constexpr int XSTRIDE = FCHUNK + 1;         // 9 (odd: conflict-free col reads)

// smem layout (floats); pair arrays first for 16B alignment
constexpr int W2P_ELE = FCHUNK * H * (H / 2) * 2;  // 2048: [f][h][kp]{lo,hi}
constexpr int W1D_ELE = FCHUNK * H * 2;            // 256 dup pairs
constexpr int W3P_ELE = FCHUNK * (H / 2) * 2;      // 128: [f][kp]{lo,hi}
constexpr int SX_ELE  = ROWS * XSTRIDE;            // 4608
constexpr int SMEM_FLOATS = W2P_ELE + 2 * W1D_ELE + FCHUNK * H + W3P_ELE
                          + 2 * FCHUNK + SX_ELE;
constexpr int SMEM_BYTES  = SMEM_FLOATS * (int)sizeof(float);  // ~30.2KB

__device__ __forceinline__ ull fma2(ull a, ull b, ull c) {
    ull d;
    asm("fma.rn.f32x2 %0, %1, %2, %3;" : "=l"(d) : "l"(a), "l"(b), "l"(c));
    return d;
}
__device__ __forceinline__ ull pack2(float lo, float hi) {
    ull d;
    asm("mov.b64 %0, {%1, %2};" : "=l"(d) : "f"(lo), "f"(hi));
    return d;
}
__device__ __forceinline__ void unpack2(ull v, float& lo, float& hi) {
    asm("mov.b64 {%0, %1}, %2;" : "=f"(lo), "=f"(hi) : "l"(v));
}
__device__ __forceinline__ ull relu2(ull v) {
    float lo, hi;
    unpack2(v, lo, hi);
    return pack2(fmaxf(lo, 0.0f), fmaxf(hi, 0.0f));
}

__global__ void igann_init_kernel(float* __restrict__ out,
                                  const float* __restrict__ bias_b) {
    int i = blockIdx.x * blockDim.x + threadIdx.x;
    if (i < B_TOTAL) out[i] = bias_b[0];
}

__global__ __launch_bounds__(BLOCK, 3)
void igann_kernel(const float* __restrict__ x,
                  const float* __restrict__ linear_a,
                  const float* __restrict__ W1,
                  const float* __restrict__ b1,
                  const float* __restrict__ W2,
                  const float* __restrict__ b2,
                  const float* __restrict__ W3,
                  const float* __restrict__ b3,
                  float* __restrict__ out) {
    extern __shared__ float smem[];
    float* sW2p = smem;                      // [FCHUNK][H][H/2][2]  k-pair interleaved
    float* sW1d = sW2p + W2P_ELE;            // [FCHUNK][H][2] duplicated
    float* sB1d = sW1d + W1D_ELE;            // [FCHUNK][H][2] duplicated
    float* sW3p = sB1d + W1D_ELE;            // [FCHUNK][H/2][2] k-pair
    float* sB2  = sW3p + W3P_ELE;            // [FCHUNK][H] (read as ull pairs)
    float* sB3  = sB2  + FCHUNK * H;         // [FCHUNK]
    float* sA   = sB3  + FCHUNK;             // [FCHUNK]
    float* sx   = sA   + FCHUNK;             // [ROWS][XSTRIDE]

    const int tid  = threadIdx.x;
    const int row0 = blockIdx.x * ROWS;
    const int f0   = blockIdx.y * FCHUNK;

    // ---- stage small weights ----
    {
        const int wbase = f0 * H;
        for (int i = tid; i < FCHUNK * H; i += BLOCK) {
            const float w = W1[wbase + i];
            sW1d[2 * i] = w; sW1d[2 * i + 1] = w;
            const float bb = b1[wbase + i];
            sB1d[2 * i] = bb; sB1d[2 * i + 1] = bb;
            sB2[i]  = b2[wbase + i];
            sW3p[i] = W3[wbase + i];   // [f][h] contiguous == [f][kp]{lo,hi}
        }
        if (tid < FCHUNK) {
            sB3[tid] = b3[f0 + tid];
            sA[tid]  = linear_a[f0 + tid];
        }
    }
    // ---- stage W2 k-pair interleaved: sW2p[f][h][kp] = {W2[f][2kp][h], W2[f][2kp+1][h]}
    for (int i = tid; i < FCHUNK * H * (H / 2); i += BLOCK) {
        const int f  = i >> 7;          // / (H * H/2)
        const int h  = (i >> 3) & 15;
        const int kp = i & 7;
        const float* src = W2 + (f0 + f) * (H * H) + h;
        sW2p[2 * i]     = src[(2 * kp) * H];
        sW2p[2 * i + 1] = src[(2 * kp + 1) * H];
    }
    // ---- stage x tile: float4 global loads ----
    for (int i = tid; i < ROWS * (FCHUNK / 4); i += BLOCK) {
        const int r = i >> 1;           // 2 quads per row
        const int q = i & 1;
        const float4 v = *(const float4*)(x + (row0 + r) * F_TOTAL + f0 + 4 * q);
        float* dst = sx + r * XSTRIDE + 4 * q;
        dst[0] = v.x; dst[1] = v.y; dst[2] = v.z; dst[3] = v.w;
    }
    __syncthreads();

    float accL0 = 0.0f, accL1 = 0.0f;
    ull accP0 = pack2(0.0f, 0.0f), accP1 = pack2(0.0f, 0.0f);

    #pragma unroll 1
    for (int f = 0; f < FCHUNK; ++f) {
        const float xv0 = sx[tid * XSTRIDE + f];
        const float xv1 = sx[(tid + BLOCK) * XSTRIDE + f];
        const ull xp = pack2(xv0, xv1);

        const ull* w1d = (const ull*)sW1d + f * H;
        const ull* b1d = (const ull*)sB1d + f * H;
        const ull* b2p = (const ull*)(sB2 + f * H);               // 8 k-pairs
        const ull* w3p = (const ull*)sW3p + f * (H / 2);          // 8 k-pairs
        const ulonglong2* w2q = (const ulonglong2*)sW2p + f * 64; // 16h x 4 quads

        // init accumulators from b2
        ull t0[8], t1[8];
        #pragma unroll
        for (int j = 0; j < 8; ++j) { t0[j] = b2p[j]; t1[j] = b2p[j]; }

        // double-buffered W2 quads
        ulonglong2 qa = w2q[0], qb = w2q[1], qc = w2q[2], qd = w2q[3];

        #pragma unroll
        for (int h = 0; h < H; ++h) {
            // prefetch next h's quads before using current ones
            ulonglong2 na, nb, nc, nd;
            if (h + 1 < H) {
                na = w2q[(h + 1) * 4 + 0];
                nb = w2q[(h + 1) * 4 + 1];
                nc = w2q[(h + 1) * 4 + 2];
                nd = w2q[(h + 1) * 4 + 3];
            }
            const ull hp = fma2(xp, w1d[h], b1d[h]);   // {h1(row0), h1(row1)}
            float ha, hb;
            unpack2(hp, ha, hb);
            ha = fmaxf(ha, 0.0f);
            hb = fmaxf(hb, 0.0f);
            const ull d0 = pack2(ha, ha);
            const ull d1 = pack2(hb, hb);

            t0[0] = fma2(d0, qa.x, t0[0]);  t1[0] = fma2(d1, qa.x, t1[0]);
            t0[1] = fma2(d0, qa.y, t0[1]);  t1[1] = fma2(d1, qa.y, t1[1]);
            t0[2] = fma2(d0, qb.x, t0[2]);  t1[2] = fma2(d1, qb.x, t1[2]);
            t0[3] = fma2(d0, qb.y, t0[3]);  t1[3] = fma2(d1, qb.y, t1[3]);
            t0[4] = fma2(d0, qc.x, t0[4]);  t1[4] = fma2(d1, qc.x, t1[4]);
            t0[5] = fma2(d0, qc.y, t0[5]);  t1[5] = fma2(d1, qc.y, t1[5]);
            t0[6] = fma2(d0, qd.x, t0[6]);  t1[6] = fma2(d1, qd.x, t1[6]);
            t0[7] = fma2(d0, qd.y, t0[7]);  t1[7] = fma2(d1, qd.y, t1[7]);

            if (h + 1 < H) { qa = na; qb = nb; qc = nc; qd = nd; }
        }

        // epilogue: accP += relu2(t) * w3 pair
        #pragma unroll
        for (int j = 0; j < 8; ++j) {
            const ull w3 = w3p[j];
            accP0 = fma2(relu2(t0[j]), w3, accP0);
            accP1 = fma2(relu2(t1[j]), w3, accP1);
        }

        const float bf = sB3[f];
        const float af = sA[f];
        accL0 = fmaf(xv0, af, accL0 + bf);
        accL1 = fmaf(xv1, af, accL1 + bf);
    }

    {
        float lo, hi;
        unpack2(accP0, lo, hi);
        atomicAdd(&out[row0 + tid], accL0 + lo + hi);
        unpack2(accP1, lo, hi);
        atomicAdd(&out[row0 + tid + BLOCK], accL1 + lo + hi);
    }
}

extern "C" void kernel_launch(void* const* d_in, const int* in_sizes, int n_in,
                              void* d_out, int out_size) {
    const float* x        = (const float*)d_in[0];
    const float* linear_a = (const float*)d_in[1];
    const float* bias_b   = (const float*)d_in[2];
    const float* W1       = (const float*)d_in[3];
    const float* b1       = (const float*)d_in[4];
    const float* W2       = (const float*)d_in[5];
    const float* b2       = (const float*)d_in[6];
    const float* W3       = (const float*)d_in[7];
    const float* b3       = (const float*)d_in[8];
    float* out = (float*)d_out;

    cudaFuncSetAttribute(igann_kernel,
                         cudaFuncAttributeMaxDynamicSharedMemorySize, SMEM_BYTES);

    igann_init_kernel<<<(B_TOTAL + 255) / 256, 256>>>(out, bias_b);

    dim3 grid(NBTILE, NCHUNK);
    igann_kernel<<<grid, BLOCK, SMEM_BYTES>>>(x, linear_a, W1, b1, W2, b2, W3, b3, out);
}